// round 1
// baseline (speedup 1.0000x reference)
#include <cuda_runtime.h>
#include <cuda_bf16.h>

#define N 8192
#define C 10
#define D 6
#define JC 1024   // j-chunk per GEMV block

// Scratch (static device globals; allocation-free per harness rules)
__device__ float g_Ksp[(size_t)N * N];   // 268 MB
__device__ float g_Kbl[(size_t)N * N];   // 268 MB
__device__ float g_P[C * N];
__device__ float g_OSP[C * N];
__device__ float g_OBL[C * N];
__device__ float g_A[C * C];             // CM @ SW
__device__ float g_B[C * C];             // CM @ BW

// ---------------------------------------------------------------------------
// Build both kernel matrices once. Tile: 256 j (threads) x 32 i (loop).
// K_sp[i,j] = exp(-0.5 * ||(f_i - f_j)[:3]||^2 / 64), K_bl over all 6 dims.
// ---------------------------------------------------------------------------
__global__ __launch_bounds__(256) void build_K(const float* __restrict__ feat) {
    __shared__ float fi[32][D];
    const int j = blockIdx.x * 256 + threadIdx.x;
    const int ibase = blockIdx.y * 32;

    if (threadIdx.x < 32 * D) {
        int r = threadIdx.x / D, d = threadIdx.x % D;
        fi[r][d] = feat[d * N + ibase + r];
    }
    __syncthreads();

    float fj[D];
#pragma unroll
    for (int d = 0; d < D; d++) fj[d] = feat[d * N + j];

#pragma unroll 4
    for (int r = 0; r < 32; r++) {
        float dsp = 0.f, dbl = 0.f;
#pragma unroll
        for (int d = 0; d < D; d++) {
            float df = fi[r][d] - fj[d];
            dbl += df * df;
            if (d < 3) dsp += df * df;
        }
        int i = ibase + r;
        g_Ksp[(size_t)i * N + j] = __expf(-0.5f * (1.0f / 64.0f) * dsp);
        g_Kbl[(size_t)i * N + j] = __expf(-0.5f * dbl);
    }
}

// ---------------------------------------------------------------------------
// A = CM @ SW, B = CM @ BW  (10x10, one tiny block)
// ---------------------------------------------------------------------------
__global__ void ab_k(const float* __restrict__ sw, const float* __restrict__ bw,
                     const float* __restrict__ cm) {
    int t = threadIdx.x;
    if (t < C * C) {
        int r = t / C, c = t % C;
        float a = 0.f, b = 0.f;
        for (int k = 0; k < C; k++) {
            a += cm[r * C + k] * sw[k * C + c];
            b += cm[r * C + k] * bw[k * C + c];
        }
        g_A[t] = a;
        g_B[t] = b;
    }
}

// ---------------------------------------------------------------------------
// Column-wise softmax over classes: g_P = softmax(qin, axis=0)
// ---------------------------------------------------------------------------
__global__ __launch_bounds__(256) void softmax_k(const float* __restrict__ qin) {
    int i = blockIdx.x * blockDim.x + threadIdx.x;
    if (i >= N) return;
    float v[C];
    float m = -1e30f;
#pragma unroll
    for (int c = 0; c < C; c++) {
        v[c] = qin[c * N + i];
        m = fmaxf(m, v[c]);
    }
    float s = 0.f;
#pragma unroll
    for (int c = 0; c < C; c++) {
        v[c] = __expf(v[c] - m);
        s += v[c];
    }
    float inv = 1.0f / s;
#pragma unroll
    for (int c = 0; c < C; c++) g_P[c * N + i] = v[c] * inv;
}

__global__ void zero_k() {
    int idx = blockIdx.x * blockDim.x + threadIdx.x;
    if (idx < C * N) {
        g_OSP[idx] = 0.f;
        g_OBL[idx] = 0.f;
    }
}

// ---------------------------------------------------------------------------
// Out[c,i] = sum_j K[i,j] * P[c,j].  grid = (i_tiles=256, j_chunks=8, 2 filters).
// Block: 8 warps; warp handles 4 consecutive rows i, lanes stride j.
// P chunk staged in smem (conflict-free: lane -> bank).
// ---------------------------------------------------------------------------
__global__ __launch_bounds__(256) void gemv_k() {
    __shared__ float psm[C][JC];

    const float* __restrict__ Kmat = blockIdx.z ? g_Kbl : g_Ksp;
    float* __restrict__ outp = blockIdx.z ? g_OBL : g_OSP;

    const int jbase = blockIdx.y * JC;
    const int tid = threadIdx.x;

    // stage P tile
    for (int idx = tid; idx < C * JC; idx += 256) {
        int c = idx / JC, j = idx - c * JC;
        psm[c][j] = g_P[c * N + jbase + j];
    }
    __syncthreads();

    const int warp = tid >> 5, lane = tid & 31;
    const int i0 = blockIdx.x * 32 + warp * 4;

    float acc[4][C];
#pragma unroll
    for (int r = 0; r < 4; r++)
#pragma unroll
        for (int c = 0; c < C; c++) acc[r][c] = 0.f;

    const float* __restrict__ kbase = Kmat + (size_t)i0 * N + jbase;

    for (int j = lane; j < JC; j += 32) {
        float pv[C];
#pragma unroll
        for (int c = 0; c < C; c++) pv[c] = psm[c][j];
#pragma unroll
        for (int r = 0; r < 4; r++) {
            float kv = __ldg(kbase + (size_t)r * N + j);
#pragma unroll
            for (int c = 0; c < C; c++) acc[r][c] = fmaf(kv, pv[c], acc[r][c]);
        }
    }

    // warp-reduce each accumulator, lane 0 commits
#pragma unroll
    for (int r = 0; r < 4; r++) {
#pragma unroll
        for (int c = 0; c < C; c++) {
            float v = acc[r][c];
            v += __shfl_xor_sync(0xFFFFFFFFu, v, 16);
            v += __shfl_xor_sync(0xFFFFFFFFu, v, 8);
            v += __shfl_xor_sync(0xFFFFFFFFu, v, 4);
            v += __shfl_xor_sync(0xFFFFFFFFu, v, 2);
            v += __shfl_xor_sync(0xFFFFFFFFu, v, 1);
            if (lane == 0) atomicAdd(&outp[c * N + i0 + r], v);
        }
    }
}

// ---------------------------------------------------------------------------
// q = unaries - (A @ sp_out + B @ bl_out)
// ---------------------------------------------------------------------------
__global__ __launch_bounds__(256) void epilogue_k(const float* __restrict__ unaries,
                                                  float* __restrict__ qout) {
    __shared__ float As[C * C], Bs[C * C];
    if (threadIdx.x < C * C) {
        As[threadIdx.x] = g_A[threadIdx.x];
        Bs[threadIdx.x] = g_B[threadIdx.x];
    }
    __syncthreads();

    int i = blockIdx.x * blockDim.x + threadIdx.x;
    if (i >= N) return;

    float sp[C], bl[C];
#pragma unroll
    for (int k = 0; k < C; k++) {
        sp[k] = g_OSP[k * N + i];
        bl[k] = g_OBL[k * N + i];
    }
#pragma unroll
    for (int c = 0; c < C; c++) {
        float pair = 0.f;
#pragma unroll
        for (int k = 0; k < C; k++)
            pair += As[c * C + k] * sp[k] + Bs[c * C + k] * bl[k];
        qout[c * N + i] = unaries[c * N + i] - pair;
    }
}

// ---------------------------------------------------------------------------
extern "C" void kernel_launch(void* const* d_in, const int* in_sizes, int n_in,
                              void* d_out, int out_size) {
    const float* unaries = (const float*)d_in[0];
    const float* feat = (const float*)d_in[1];
    const float* sw = (const float*)d_in[2];
    const float* bw = (const float*)d_in[3];
    const float* cm = (const float*)d_in[4];
    float* qout = (float*)d_out;

    build_K<<<dim3(N / 256, N / 32), 256>>>(feat);
    ab_k<<<1, 128>>>(sw, bw, cm);

    const float* qsrc = unaries;
    for (int it = 0; it < 5; it++) {
        softmax_k<<<N / 256, 256>>>(qsrc);
        zero_k<<<(C * N + 255) / 256, 256>>>();
        gemv_k<<<dim3(N / 32, N / JC, 2), 256>>>();
        epilogue_k<<<N / 256, 256>>>(unaries, qout);
        qsrc = qout;
    }
}

// round 4
// speedup vs baseline: 1.3546x; 1.3546x over previous
#include <cuda_runtime.h>
#include <cuda_fp16.h>

#define N 8192
#define C 10
#define Dd 6
#define JC 1024
#define BI 64

__device__ __half g_Ksp[(size_t)N * N];   // 134 MB
__device__ __half g_Kbl[(size_t)N * N];   // 134 MB
__device__ float g_P[C * N];
__device__ float g_OSP[C * N];
__device__ float g_OBL[C * N];
__device__ float g_A[C * C];
__device__ float g_B[C * C];

// ---- f32x2 packed helpers ----
__device__ __forceinline__ unsigned long long pk2(float lo, float hi) {
    unsigned long long r;
    asm("mov.b64 %0, {%1, %2};" : "=l"(r) : "f"(lo), "f"(hi));
    return r;
}
__device__ __forceinline__ float2 upk2(unsigned long long v) {
    float2 r;
    asm("mov.b64 {%0, %1}, %2;" : "=f"(r.x), "=f"(r.y) : "l"(v));
    return r;
}
__device__ __forceinline__ unsigned long long ffma2(unsigned long long a,
                                                    unsigned long long b,
                                                    unsigned long long c) {
    unsigned long long d;
    asm("fma.rn.f32x2 %0, %1, %2, %3;" : "=l"(d) : "l"(a), "l"(b), "l"(c));
    return d;
}

// ---------------------------------------------------------------------------
// Build both kernel matrices (fp16) once. Dot-product distance form:
// d2 = |fi|^2 + |fj|^2 - 2 fi.fj ; Ksp = exp(-d3/128), Kbl = exp(-0.5 d6).
// Thread handles 2 consecutive j (half2 store) x BI rows.
// ---------------------------------------------------------------------------
__global__ __launch_bounds__(256) void build_K(const float* __restrict__ feat) {
    __shared__ float fis[Dd][BI];
    __shared__ float a3s[BI], a6s[BI];

    const int ib = blockIdx.y * BI;
    const int jp = blockIdx.x * 256 + threadIdx.x;
    const int j0 = jp * 2;

    if (threadIdx.x < BI) {
        float s3 = 0.f, s6 = 0.f;
#pragma unroll
        for (int d = 0; d < Dd; d++) {
            float v = feat[d * N + ib + threadIdx.x];
            fis[d][threadIdx.x] = v;
            if (d < 3) s3 += v * v; else s6 += v * v;
        }
        a3s[threadIdx.x] = s3;
        a6s[threadIdx.x] = s3 + s6;
    }
    __syncthreads();

    float fj[2][Dd], b3[2], b6[2];
#pragma unroll
    for (int t = 0; t < 2; t++) {
        float s3 = 0.f, s6 = 0.f;
#pragma unroll
        for (int d = 0; d < Dd; d++) {
            float v = feat[d * N + j0 + t];
            fj[t][d] = v;
            if (d < 3) s3 += v * v; else s6 += v * v;
        }
        b3[t] = s3;
        b6[t] = s3 + s6;
    }

#pragma unroll 4
    for (int r = 0; r < BI; r++) {
        __half2 hsp, hbl;
        float ksp[2], kbl[2];
#pragma unroll
        for (int t = 0; t < 2; t++) {
            float s3 = 0.f, s6 = 0.f;
#pragma unroll
            for (int d = 0; d < 3; d++) s3 = fmaf(fis[d][r], fj[t][d], s3);
            s6 = s3;
#pragma unroll
            for (int d = 3; d < Dd; d++) s6 = fmaf(fis[d][r], fj[t][d], s6);
            float d3 = a3s[r] + b3[t] - 2.f * s3;
            float d6 = a6s[r] + b6[t] - 2.f * s6;
            ksp[t] = __expf(d3 * (-1.f / 128.f));
            kbl[t] = __expf(-0.5f * d6);
        }
        hsp = __floats2half2_rn(ksp[0], ksp[1]);
        hbl = __floats2half2_rn(kbl[0], kbl[1]);
        size_t off = (size_t)(ib + r) * N + j0;
        *(__half2*)&g_Ksp[off] = hsp;
        *(__half2*)&g_Kbl[off] = hbl;
    }
}

// ---------------------------------------------------------------------------
__global__ void ab_k(const float* __restrict__ sw, const float* __restrict__ bw,
                     const float* __restrict__ cm) {
    int t = threadIdx.x;
    if (t < C * C) {
        int r = t / C, c = t % C;
        float a = 0.f, b = 0.f;
        for (int k = 0; k < C; k++) {
            a += cm[r * C + k] * sw[k * C + c];
            b += cm[r * C + k] * bw[k * C + c];
        }
        g_A[t] = a;
        g_B[t] = b;
    }
}

// ---------------------------------------------------------------------------
__global__ __launch_bounds__(256) void softmax_k(const float* __restrict__ qin) {
    int i = blockIdx.x * blockDim.x + threadIdx.x;
    if (i >= N) return;
    float v[C];
    float m = -1e30f;
#pragma unroll
    for (int c = 0; c < C; c++) {
        v[c] = qin[c * N + i];
        m = fmaxf(m, v[c]);
    }
    float s = 0.f;
#pragma unroll
    for (int c = 0; c < C; c++) {
        v[c] = __expf(v[c] - m);
        s += v[c];
    }
    float inv = 1.0f / s;
#pragma unroll
    for (int c = 0; c < C; c++) g_P[c * N + i] = v[c] * inv;
}

// ---------------------------------------------------------------------------
// Out[c,i] = sum_j K[i,j] * P[c,j].  Block: 8 warps x 4 rows = 32 rows,
// full j-loop (no atomics). Lane <-> consecutive j-pair; K as half2 LDG,
// P chunk staged in smem as packed f32x2; MAC via fma.rn.f32x2.
// grid = (N/32, 2 filters)
// ---------------------------------------------------------------------------
__global__ __launch_bounds__(256, 2) void gemv_k() {
    __shared__ unsigned long long psm[C][JC / 2];   // 40 KB

    const __half* __restrict__ K = blockIdx.y ? g_Kbl : g_Ksp;
    float* __restrict__ outp = blockIdx.y ? g_OBL : g_OSP;

    const int tid = threadIdx.x;
    const int warp = tid >> 5, lane = tid & 31;
    const int i0 = blockIdx.x * 32 + warp * 4;
    const __half* __restrict__ kb = K + (size_t)i0 * N;

    unsigned long long acc[4][C];
#pragma unroll
    for (int r = 0; r < 4; r++)
#pragma unroll
        for (int c = 0; c < C; c++) acc[r][c] = 0ull;

    for (int cb = 0; cb < N; cb += JC) {
        // stage P chunk as packed f32x2
        for (int idx = tid; idx < C * (JC / 2); idx += 256) {
            int c = idx / (JC / 2), p = idx - c * (JC / 2);
            float2 t = *(const float2*)&g_P[c * N + cb + p * 2];
            psm[c][p] = pk2(t.x, t.y);
        }
        __syncthreads();

#pragma unroll 2
        for (int jj = 0; jj < JC / 64; jj++) {   // 16 steps, 32 jpairs/warp each
            const int jp = jj * 32 + lane;
            const int j = cb + jp * 2;

            unsigned int kr[4];
#pragma unroll
            for (int r = 0; r < 4; r++)
                kr[r] = *(const unsigned int*)(kb + (size_t)r * N + j);

            unsigned long long pv[C];
#pragma unroll
            for (int c = 0; c < C; c++) pv[c] = psm[c][jp];

#pragma unroll
            for (int r = 0; r < 4; r++) {
                float2 kf = __half22float2(*(__half2*)&kr[r]);
                unsigned long long kv = pk2(kf.x, kf.y);
#pragma unroll
                for (int c = 0; c < C; c++) acc[r][c] = ffma2(kv, pv[c], acc[r][c]);
            }
        }
        __syncthreads();
    }

    // reduce: fold packed halves, then warp tree-reduce, lane 0 stores
#pragma unroll
    for (int r = 0; r < 4; r++) {
#pragma unroll
        for (int c = 0; c < C; c++) {
            float2 t = upk2(acc[r][c]);
            float v = t.x + t.y;
            v += __shfl_xor_sync(0xFFFFFFFFu, v, 16);
            v += __shfl_xor_sync(0xFFFFFFFFu, v, 8);
            v += __shfl_xor_sync(0xFFFFFFFFu, v, 4);
            v += __shfl_xor_sync(0xFFFFFFFFu, v, 2);
            v += __shfl_xor_sync(0xFFFFFFFFu, v, 1);
            if (lane == 0) outp[c * N + i0 + r] = v;
        }
    }
}

// ---------------------------------------------------------------------------
__global__ __launch_bounds__(256) void epilogue_k(const float* __restrict__ unaries,
                                                  float* __restrict__ qout) {
    __shared__ float As[C * C], Bs[C * C];
    if (threadIdx.x < C * C) {
        As[threadIdx.x] = g_A[threadIdx.x];
        Bs[threadIdx.x] = g_B[threadIdx.x];
    }
    __syncthreads();

    int i = blockIdx.x * blockDim.x + threadIdx.x;
    if (i >= N) return;

    float sp[C], bl[C];
#pragma unroll
    for (int k = 0; k < C; k++) {
        sp[k] = g_OSP[k * N + i];
        bl[k] = g_OBL[k * N + i];
    }
#pragma unroll
    for (int c = 0; c < C; c++) {
        float pair = 0.f;
#pragma unroll
        for (int k = 0; k < C; k++)
            pair += As[c * C + k] * sp[k] + Bs[c * C + k] * bl[k];
        qout[c * N + i] = unaries[c * N + i] - pair;
    }
}

// ---------------------------------------------------------------------------
extern "C" void kernel_launch(void* const* d_in, const int* in_sizes, int n_in,
                              void* d_out, int out_size) {
    const float* unaries = (const float*)d_in[0];
    const float* feat = (const float*)d_in[1];
    const float* sw = (const float*)d_in[2];
    const float* bw = (const float*)d_in[3];
    const float* cm = (const float*)d_in[4];
    float* qout = (float*)d_out;

    build_K<<<dim3(N / 512, N / BI), 256>>>(feat);
    ab_k<<<1, 128>>>(sw, bw, cm);

    const float* qsrc = unaries;
    for (int it = 0; it < 5; it++) {
        softmax_k<<<N / 256, 256>>>(qsrc);
        gemv_k<<<dim3(N / 32, 2), 256>>>();
        epilogue_k<<<N / 256, 256>>>(unaries, qout);
        qsrc = qout;
    }
}

// round 8
// speedup vs baseline: 2.0668x; 1.5257x over previous
#include <cuda_runtime.h>
#include <cuda_fp16.h>

#define N 8192
#define C 10
#define Dd 6
#define JC 512    // j-chunk per gemv block
#define IT 512    // i-tile per gemv block (4 warps x 128)
#define BI 64

__device__ __half g_Ksp[(size_t)N * N];   // 134 MB
__device__ __half g_Kbl[(size_t)N * N];   // 134 MB
__device__ float g_P[C * N];
__device__ float g_OSP[C * N];
__device__ float g_OBL[C * N];
__device__ float g_A[C * C];
__device__ float g_B[C * C];

// ---- f32x2 packed helpers ----
__device__ __forceinline__ unsigned long long pk2(float lo, float hi) {
    unsigned long long r;
    asm("mov.b64 %0, {%1, %2};" : "=l"(r) : "f"(lo), "f"(hi));
    return r;
}
__device__ __forceinline__ float2 upk2(unsigned long long v) {
    float2 r;
    asm("mov.b64 {%0, %1}, %2;" : "=f"(r.x), "=f"(r.y) : "l"(v));
    return r;
}
__device__ __forceinline__ unsigned long long ffma2(unsigned long long a,
                                                    unsigned long long b,
                                                    unsigned long long c) {
    unsigned long long d;
    asm("fma.rn.f32x2 %0, %1, %2, %3;" : "=l"(d) : "l"(a), "l"(b), "l"(c));
    return d;
}

// ---------------------------------------------------------------------------
// Build both kernel matrices (fp16) once. Dot-product distance form.
// ---------------------------------------------------------------------------
__global__ __launch_bounds__(256) void build_K(const float* __restrict__ feat) {
    __shared__ float fis[Dd][BI];
    __shared__ float a3s[BI], a6s[BI];

    const int ib = blockIdx.y * BI;
    const int jp = blockIdx.x * 256 + threadIdx.x;
    const int j0 = jp * 2;

    if (threadIdx.x < BI) {
        float s3 = 0.f, s6 = 0.f;
#pragma unroll
        for (int d = 0; d < Dd; d++) {
            float v = feat[d * N + ib + threadIdx.x];
            fis[d][threadIdx.x] = v;
            if (d < 3) s3 += v * v; else s6 += v * v;
        }
        a3s[threadIdx.x] = s3;
        a6s[threadIdx.x] = s3 + s6;
    }
    __syncthreads();

    float fj[2][Dd], b3[2], b6[2];
#pragma unroll
    for (int t = 0; t < 2; t++) {
        float s3 = 0.f, s6 = 0.f;
#pragma unroll
        for (int d = 0; d < Dd; d++) {
            float v = feat[d * N + j0 + t];
            fj[t][d] = v;
            if (d < 3) s3 += v * v; else s6 += v * v;
        }
        b3[t] = s3;
        b6[t] = s3 + s6;
    }

#pragma unroll 4
    for (int r = 0; r < BI; r++) {
        float ksp[2], kbl[2];
#pragma unroll
        for (int t = 0; t < 2; t++) {
            float s3 = 0.f, s6 = 0.f;
#pragma unroll
            for (int d = 0; d < 3; d++) s3 = fmaf(fis[d][r], fj[t][d], s3);
            s6 = s3;
#pragma unroll
            for (int d = 3; d < Dd; d++) s6 = fmaf(fis[d][r], fj[t][d], s6);
            float d3 = a3s[r] + b3[t] - 2.f * s3;
            float d6 = a6s[r] + b6[t] - 2.f * s6;
            ksp[t] = __expf(d3 * (-1.f / 128.f));
            kbl[t] = __expf(-0.5f * d6);
        }
        size_t off = (size_t)(ib + r) * N + j0;
        *(__half2*)&g_Ksp[off] = __floats2half2_rn(ksp[0], ksp[1]);
        *(__half2*)&g_Kbl[off] = __floats2half2_rn(kbl[0], kbl[1]);
    }
}

// ---------------------------------------------------------------------------
__global__ void ab_k(const float* __restrict__ sw, const float* __restrict__ bw,
                     const float* __restrict__ cm) {
    int t = threadIdx.x;
    if (t < C * C) {
        int r = t / C, c = t % C;
        float a = 0.f, b = 0.f;
        for (int k = 0; k < C; k++) {
            a += cm[r * C + k] * sw[k * C + c];
            b += cm[r * C + k] * bw[k * C + c];
        }
        g_A[t] = a;
        g_B[t] = b;
    }
}

// ---------------------------------------------------------------------------
// Softmax over classes; also zeroes the gemv accumulators (free here).
// ---------------------------------------------------------------------------
__global__ __launch_bounds__(256) void softmax_k(const float* __restrict__ qin) {
    int i = blockIdx.x * blockDim.x + threadIdx.x;
    if (i >= N) return;
    float v[C];
    float m = -1e30f;
#pragma unroll
    for (int c = 0; c < C; c++) {
        v[c] = qin[c * N + i];
        m = fmaxf(m, v[c]);
    }
    float s = 0.f;
#pragma unroll
    for (int c = 0; c < C; c++) {
        v[c] = __expf(v[c] - m);
        s += v[c];
    }
    float inv = 1.0f / s;
#pragma unroll
    for (int c = 0; c < C; c++) {
        g_P[c * N + i] = v[c] * inv;
        g_OSP[c * N + i] = 0.f;
        g_OBL[c * N + i] = 0.f;
    }
}

// ---------------------------------------------------------------------------
// Out[c,i] += sum_{j in chunk} K[j,i] * P[c,j]   (uses K symmetry: K[j,i]=K[i,j])
// Lane owns i-columns (coalesced LDG over K row j); P[c,j] is a warp-uniform
// broadcast LDS of a duplicated f32x2. Thread: 2 i-pairs (ia, ia+64).
// grid = (N/IT, N/JC, 2); block = 128 threads (4 warps x 128 i).
// ---------------------------------------------------------------------------
__global__ __launch_bounds__(128) void gemv_k() {
    __shared__ unsigned long long psm[C][JC];   // duplicated (p,p) pairs, 40 KB

    const __half* __restrict__ K = blockIdx.z ? g_Kbl : g_Ksp;
    float* __restrict__ outp = blockIdx.z ? g_OBL : g_OSP;

    const int cb = blockIdx.y * JC;
    const int tid = threadIdx.x;

    // stage P chunk, duplicating each value into both f32x2 lanes
    for (int idx = tid; idx < C * JC; idx += 128) {
        int c = idx >> 9, j = idx & (JC - 1);
        float p = g_P[c * N + cb + j];
        psm[c][j] = pk2(p, p);
    }
    __syncthreads();

    const int warp = tid >> 5, lane = tid & 31;
    const int ia = blockIdx.x * IT + warp * 128 + 2 * lane;

    unsigned long long acc0[C], acc1[C];
#pragma unroll
    for (int c = 0; c < C; c++) { acc0[c] = 0ull; acc1[c] = 0ull; }

    for (int jj = 0; jj < JC; jj += 4) {
        unsigned int kra[4], krb[4];
#pragma unroll
        for (int u = 0; u < 4; u++) {
            const __half* rp = K + (size_t)(cb + jj + u) * N + ia;
            kra[u] = *(const unsigned int*)rp;
            krb[u] = *(const unsigned int*)(rp + 64);
        }
#pragma unroll
        for (int u = 0; u < 4; u++) {
            float2 fa = __half22float2(*(__half2*)&kra[u]);
            float2 fb = __half22float2(*(__half2*)&krb[u]);
            unsigned long long kva = pk2(fa.x, fa.y);
            unsigned long long kvb = pk2(fb.x, fb.y);
#pragma unroll
            for (int c = 0; c < C; c++) {
                unsigned long long pv = psm[c][jj + u];
                acc0[c] = ffma2(kva, pv, acc0[c]);
                acc1[c] = ffma2(kvb, pv, acc1[c]);
            }
        }
    }

    // commit: each (c, i) owned by exactly one thread within this block;
    // cross-chunk accumulation via fp32 atomics (16 contributions per output)
#pragma unroll
    for (int c = 0; c < C; c++) {
        float2 a = upk2(acc0[c]);
        float2 b = upk2(acc1[c]);
        float* o = outp + c * N + ia;
        atomicAdd(o, a.x);
        atomicAdd(o + 1, a.y);
        atomicAdd(o + 64, b.x);
        atomicAdd(o + 65, b.y);
    }
}

// ---------------------------------------------------------------------------
__global__ __launch_bounds__(256) void epilogue_k(const float* __restrict__ unaries,
                                                  float* __restrict__ qout) {
    __shared__ float As[C * C], Bs[C * C];
    if (threadIdx.x < C * C) {
        As[threadIdx.x] = g_A[threadIdx.x];
        Bs[threadIdx.x] = g_B[threadIdx.x];
    }
    __syncthreads();

    int i = blockIdx.x * blockDim.x + threadIdx.x;
    if (i >= N) return;

    float sp[C], bl[C];
#pragma unroll
    for (int k = 0; k < C; k++) {
        sp[k] = g_OSP[k * N + i];
        bl[k] = g_OBL[k * N + i];
    }
#pragma unroll
    for (int c = 0; c < C; c++) {
        float pair = 0.f;
#pragma unroll
        for (int k = 0; k < C; k++)
            pair += As[c * C + k] * sp[k] + Bs[c * C + k] * bl[k];
        qout[c * N + i] = unaries[c * N + i] - pair;
    }
}

// ---------------------------------------------------------------------------
extern "C" void kernel_launch(void* const* d_in, const int* in_sizes, int n_in,
                              void* d_out, int out_size) {
    const float* unaries = (const float*)d_in[0];
    const float* feat = (const float*)d_in[1];
    const float* sw = (const float*)d_in[2];
    const float* bw = (const float*)d_in[3];
    const float* cm = (const float*)d_in[4];
    float* qout = (float*)d_out;

    build_K<<<dim3(N / 512, N / BI), 256>>>(feat);
    ab_k<<<1, 128>>>(sw, bw, cm);

    const float* qsrc = unaries;
    for (int it = 0; it < 5; it++) {
        softmax_k<<<N / 256, 256>>>(qsrc);
        gemv_k<<<dim3(N / IT, N / JC, 2), 128>>>();
        epilogue_k<<<N / 256, 256>>>(unaries, qout);
        qsrc = qout;
    }
}